// round 7
// baseline (speedup 1.0000x reference)
#include <cuda_runtime.h>
#include <math.h>

// Problem constants
constexpr int Hc   = 20;          // H
constexpr int H2c  = 40;          // 2H
constexpr int Tc   = 512;
constexpr int Dc   = 128;
constexpr int Nc   = 1024;
// Tail timesteps kept. |alpha| <= |u||z| = sqrt(2H)/H < 0.3163 rigorously,
// so truncation error <= alpha^{KT-1} ~ 3e-8 at KT=16 — far below fp32 noise.
// Likewise bias = beta*a0*alpha^511 < 1e-255 -> exact fp32 zero: dropped.
constexpr int KT   = 16;
constexpr int ROWS_PER_BLK = 4;               // samples per block
constexpr int F4_PER_ROW   = KT * Dc / 4;     // 512 float4 per sample tail
constexpr float PIf = 3.14159265358979323846f;

// ---------------------------------------------------------------------------
// Single fused kernel (one graph node).
//   recurrence(h) = (u . h) * z  (rank-1), so
//   y_n = q.x[n,T-1] + sum_{k<=KT-2} beta*alpha^{KT-2-k} (p.x[n,T-KT+k])
// cp.async issues Cw (group 0) then the 32KB x tail (group 1) at cycle 0;
// the closed-form setup runs warp-parallel (3 barriers total) underneath.
// ---------------------------------------------------------------------------
__global__ __launch_bounds__(256)
void urnn_fused(const float* __restrict__ x,     // (1024,512,128)
                const float* __restrict__ Cw,    // (40,128)
                const float* __restrict__ Bw,    // (1,40)
                const float* __restrict__ refl,  // (2,40)
                const float* __restrict__ theta, // (3,20)
                const float* __restrict__ mu0,   // (20,) unused (bias==0)
                float* __restrict__ out)         // (1024,)
{
    __shared__ float4 sX[ROWS_PER_BLK * F4_PER_ROW];   // 32 KB
    __shared__ float  sCw[H2c * Dc];                   // 20 KB
    __shared__ float tw_c[Hc], tw_s[Hc];
    __shared__ float e0c[Hc], e0s[Hc];
    __shared__ float z0r[Hc], z0i[Hc];
    __shared__ float e2c[Hc], e2s[Hc];
    __shared__ float r1[H2c], r2[H2c], sBw[H2c];
    __shared__ float su[H2c];
    __shared__ float so_r[Hc], so_i[Hc];
    __shared__ float sp[Dc], sq[Dc], scoef[KT];
    __shared__ float vss1s, vss2s;
    __shared__ float wsum[8];

    const int tid  = threadIdx.x;
    const int lane = tid & 31;
    const int warp = tid >> 5;

    // ---- cp.async: Cw first (group 0), then x tail (group 1) ----
    {
        const float4* cwsrc = reinterpret_cast<const float4*>(Cw);
        #pragma unroll
        for (int r = 0; r < 5; r++) {                 // 1280 float4 = 20 KB
            const int idx = tid + r * 256;
            unsigned sa = (unsigned)__cvta_generic_to_shared(
                reinterpret_cast<float4*>(sCw) + idx);
            asm volatile("cp.async.cg.shared.global [%0], [%1], 16;\n"
                         :: "r"(sa), "l"(cwsrc + idx));
        }
        asm volatile("cp.async.commit_group;\n");

        const int n0 = blockIdx.x * ROWS_PER_BLK;
        #pragma unroll
        for (int r = 0; r < 8; r++) {
            const int idx = tid + r * 256;            // 0..2047
            const int s   = idx >> 9;                 // sample within block
            const int w   = idx & (F4_PER_ROW - 1);   // float4 within sample
            const float4* src = reinterpret_cast<const float4*>(
                x + (size_t)(n0 + s) * (Tc * Dc) + (size_t)(Tc - KT) * Dc) + w;
            unsigned sa = (unsigned)__cvta_generic_to_shared(&sX[idx]);
            asm volatile("cp.async.cg.shared.global [%0], [%1], 16;\n"
                         :: "r"(sa), "l"(src));
        }
        asm volatile("cp.async.commit_group;\n");
    }

    // ---- Pre-stage (parallel): trig tables, operand staging, vss1/vss2 ----
    if (tid < Hc) {
        float s, c;
        sincosf(2.0f * PIf * (float)tid / (float)Hc, &s, &c);
        tw_c[tid] = c; tw_s[tid] = s;
        sincosf(theta[tid], &s, &c);          e0c[tid] = c; e0s[tid] = s;
        sincosf(theta[Hc + tid], &s, &c);     z0r[tid] = c - s; z0i[tid] = c + s;
        sincosf(theta[2 * Hc + tid], &s, &c); e2c[tid] = c; e2s[tid] = s;
    }
    if (tid >= 32 && tid < 32 + H2c) {
        const int j = tid - 32;
        r1[j] = refl[j]; r2[j] = refl[H2c + j]; sBw[j] = Bw[j];
    }
    if (warp == 3) {                                   // vss1 = |v1|^2
        float v = (lane < H2c) ? refl[lane] * refl[lane] : 0.f;
        if (lane + 32 < H2c) { float r = refl[lane + 32]; v += r * r; }
        #pragma unroll
        for (int off = 16; off; off >>= 1) v += __shfl_down_sync(0xffffffffu, v, off);
        if (lane == 0) vss1s = v;
    }
    if (warp == 4) {                                   // vss2 = |v2|^2
        float v = (lane < H2c) ? refl[H2c + lane] * refl[H2c + lane] : 0.f;
        if (lane + 32 < H2c) { float r = refl[H2c + lane + 32]; v += r * r; }
        #pragma unroll
        for (int off = 16; off; off >>= 1) v += __shfl_down_sync(0xffffffffu, v, off);
        if (lane == 0) vss2s = v;
    }
    __syncthreads();                                   // sync0

    // ---- Stage A (warps 0-1): u_j = Im[(w_j/sqrtH)(1 - s1 V_m conj(v1_0))] ----
    if (tid < H2c) {
        const int j = tid;
        const int m = (j < Hc) ? j : j - Hc;
        float2 w;
        if (j < Hc) w = make_float2(e0c[m], e0s[m]);
        else        w = make_float2(-e0s[m], e0c[m]);   // i * e^{i th}
        const float sc1 = 2.0f / vss1s;
        float Vx = 0.f, Vy = 0.f;
        #pragma unroll 4
        for (int k = 0; k < Hc; k++) {
            const int mm = (m * k) % Hc;
            const float ck = tw_c[mm], sk = -tw_s[mm];  // exp(-2*pi*i*mm/H)
            const float vr = r1[k], vi = r1[Hc + k];
            Vx += vr * ck - vi * sk;
            Vy += vr * sk + vi * ck;
        }
        const float v0x = r1[0], v0y = -r1[Hc];         // conj(v1_0)
        const float gx = 1.0f - sc1 * (Vx * v0x - Vy * v0y);
        const float gy =        -sc1 * (Vx * v0y + Vy * v0x);
        su[j] = (w.x * gy + w.y * gx) * (1.0f / sqrtf((float)Hc));
    }
    // ---- Stage B1 (warp 2, concurrent): o = IFFT(z0)/sqrtH ----
    if (tid >= 64 && tid < 64 + Hc) {
        const int k = tid - 64;
        float ar = 0.f, ai = 0.f;
        #pragma unroll 4
        for (int m = 0; m < Hc; m++) {
            const int mm = (m * k) % Hc;
            const float ck = tw_c[mm], sk = tw_s[mm];   // exp(+2*pi*i*mm/H)
            ar += z0r[m] * ck - z0i[m] * sk;
            ai += z0r[m] * sk + z0i[m] * ck;
        }
        const float scale = 1.0f / ((float)Hc * sqrtf((float)Hc));
        so_r[k] = ar * scale; so_i[k] = ai * scale;
    }

    // Cw prefetch must be visible after the next barrier.
    asm volatile("cp.async.wait_group 1;\n" ::: "memory");
    __syncthreads();                                   // sync1

    // ---- Warp 0: B2 + B3 + C, barrier-free (shuffle reductions) ----
    if (warp == 0) {
        const int k = lane;                            // lanes 0-19 active for data
        const bool act = (k < Hc);
        const float vr = act ? r2[k] : 0.f;
        const float vi = act ? r2[Hc + k] : 0.f;
        const float orr = act ? so_r[k] : 0.f;
        const float oii = act ? so_i[k] : 0.f;
        // B2: t2 = (2/vss2) * (v2^T o)
        float tx = vr * orr - vi * oii;
        float ty = vr * oii + vi * orr;
        #pragma unroll
        for (int off = 16; off; off >>= 1) {
            tx += __shfl_down_sync(0xffffffffu, tx, off);
            ty += __shfl_down_sync(0xffffffffu, ty, off);
        }
        const float s2 = 2.0f / vss2s;
        const float t2x = __shfl_sync(0xffffffffu, tx, 0) * s2;
        const float t2y = __shfl_sync(0xffffffffu, ty, 0) * s2;
        // B3 (registers): z = D3 * (o - t2*conj(v2))
        float szk = 0.f, szk20 = 0.f;
        if (act) {
            const float ox = orr - (t2x * vr + t2y * vi);
            const float oy = oii - (t2y * vr - t2x * vi);
            const float c = e2c[k], s = e2s[k];
            szk   = ox * c - oy * s;
            szk20 = ox * s + oy * c;
        }
        // C: alpha = u.z, beta = z.Bw (lane-parallel partials)
        float ap = 0.f, bp = 0.f;
        if (act) {
            ap = su[k] * szk + su[Hc + k] * szk20;
            bp = szk * sBw[k] + szk20 * sBw[Hc + k];
        }
        #pragma unroll
        for (int off = 16; off; off >>= 1) {
            ap += __shfl_down_sync(0xffffffffu, ap, off);
            bp += __shfl_down_sync(0xffffffffu, bp, off);
        }
        const float alpha = __shfl_sync(0xffffffffu, ap, 0);
        const float beta  = __shfl_sync(0xffffffffu, bp, 0);
        // coef ladder, per-lane (<=14 serial multiplies, parallel across lanes)
        if (lane < KT) {
            float c;
            if (lane == KT - 1) c = 1.0f;               // slot for q
            else {
                c = beta;
                for (int e = 0; e < KT - 2 - lane; e++) c *= alpha;
            }
            scoef[lane] = c;
        }
    }
    // ---- Warps 4-7 (concurrent): p = Cw^T u, q = Cw^T b from smem ----
    if (tid >= 128) {
        const int d = tid - 128;
        float p = 0.f, q = 0.f;
        #pragma unroll 8
        for (int j = 0; j < H2c; j++) {
            const float cw = sCw[j * Dc + d];
            p += su[j] * cw;
            q += sBw[j] * cw;
        }
        sp[d] = p; sq[d] = q;
    }

    // ---- Wait for x tail, then dot ----
    asm volatile("cp.async.wait_group 0;\n" ::: "memory");
    __syncthreads();                                   // sync2

    // 64 threads per sample; thread covers float4 indices st + 64r (r=0..7).
    // k = (st + 64r) >> 5 = 2r + warpInSample -> warp-uniform.
    const int s   = tid >> 6;                          // sample within block
    const int st  = tid & 63;                          // thread within sample
    const int wis = (tid >> 5) & 1;                    // warp within sample

    const float4 pv = reinterpret_cast<const float4*>(sp)[lane];
    const float4 qv = reinterpret_cast<const float4*>(sq)[lane];

    float acc = 0.f;
    #pragma unroll
    for (int r = 0; r < 8; r++) {
        const int k = 2 * r + wis;                     // timestep, warp-uniform
        const float4 xv = sX[s * F4_PER_ROW + st + r * 64];
        const float4 wv = (k == KT - 1) ? qv : pv;
        const float d = xv.x * wv.x + xv.y * wv.y + xv.z * wv.z + xv.w * wv.w;
        acc += scoef[k] * d;
    }

    #pragma unroll
    for (int off = 16; off; off >>= 1) acc += __shfl_down_sync(0xffffffffu, acc, off);
    if (lane == 0) wsum[warp] = acc;
    __syncthreads();
    if (tid < ROWS_PER_BLK)
        out[blockIdx.x * ROWS_PER_BLK + tid] = wsum[2 * tid] + wsum[2 * tid + 1];
}

extern "C" void kernel_launch(void* const* d_in, const int* in_sizes, int n_in,
                              void* d_out, int out_size)
{
    const float* inputs = (const float*)d_in[0];   // (1024, 512, 128)
    const float* C_w    = (const float*)d_in[1];   // (40, 128)
    const float* B_w    = (const float*)d_in[2];   // (1, 40)
    const float* refl   = (const float*)d_in[3];   // (2, 40)
    const float* theta  = (const float*)d_in[4];   // (3, 20)
    const float* mu0    = (const float*)d_in[5];   // (20,)
    float* out = (float*)d_out;                    // (1024,)

    urnn_fused<<<Nc / ROWS_PER_BLK, 256>>>(inputs, C_w, B_w, refl, theta, mu0, out);
}

// round 8
// speedup vs baseline: 1.0064x; 1.0064x over previous
#include <cuda_runtime.h>
#include <math.h>

// Problem constants
constexpr int Hc   = 20;          // H
constexpr int H2c  = 40;          // 2H
constexpr int Tc   = 512;
constexpr int Dc   = 128;
constexpr int Nc   = 1024;
// Tail timesteps kept. |alpha| <= |u||z| = sqrt(2H)/H < 0.3163 rigorously,
// so truncation error <= alpha^{KT-1} ~ 3e-8 at KT=16 — far below fp32 noise.
// bias = beta*a0*alpha^511 < 1e-255 -> exact fp32 zero: dropped.
constexpr int KT   = 16;
constexpr int ROWS_PER_BLK = 4;               // samples per block (grid = 256)
constexpr float PIf = 3.14159265358979323846f;

// ---------------------------------------------------------------------------
// Single fused kernel, register-resident x.
//   recurrence(h) = (u . h) * z  (rank-1), so
//   y_n = q.x[n,T-1] + sum_{k<=KT-2} beta*alpha^{KT-2-k} (p.x[n,T-KT+k])
// Thread layout: 64 threads per sample, 8 float4 per thread issued at entry.
// Setup: warp 0 -> su (Stage A); warp 1 -> B1/B2/B3 (warp-internal) then
// alpha/beta/coef; warps 4-7 -> p,q. Two barriers before the dot.
// ---------------------------------------------------------------------------
__global__ __launch_bounds__(256)
void urnn_fused(const float* __restrict__ x,     // (1024,512,128)
                const float* __restrict__ Cw,    // (40,128)
                const float* __restrict__ Bw,    // (1,40)
                const float* __restrict__ refl,  // (2,40)
                const float* __restrict__ theta, // (3,20)
                const float* __restrict__ mu0,   // unused (bias == 0)
                float* __restrict__ out)         // (1024,)
{
    __shared__ float su[H2c];
    __shared__ float sp[Dc], sq[Dc], scoef[KT];
    __shared__ float wsum[8];

    const int tid  = threadIdx.x;
    const int lane = tid & 31;
    const int warp = tid >> 5;
    const unsigned FULL = 0xffffffffu;

    // ---- x tail straight into registers (issued first, consumed last) ----
    const int s   = tid >> 6;                  // sample within block (0..3)
    const int st  = tid & 63;                  // thread within sample
    const int wis = (tid >> 5) & 1;            // warp within sample
    const float4* xp = reinterpret_cast<const float4*>(
        x + (size_t)(blockIdx.x * ROWS_PER_BLK + s) * (Tc * Dc)
          + (size_t)(Tc - KT) * Dc);
    float4 xv[8];
    #pragma unroll
    for (int r = 0; r < 8; r++) xv[r] = __ldg(xp + st + r * 64);

    // Registers carried across sync_a by warp 1
    float zr = 0.f, zi = 0.f, bwr = 0.f, bwi = 0.f;
    const bool act = (lane < Hc);

    if (warp == 0) {
        // ---- Stage A: lane m emits su[m] and su[m+20] (shared V_m) ----
        const int m = lane;
        const float vr = act ? __ldg(refl + m)      : 0.f;
        const float vi = act ? __ldg(refl + Hc + m) : 0.f;
        // vss1 (butterfly reduce -> all lanes)
        float v = vr * vr + vi * vi;
        #pragma unroll
        for (int off = 16; off; off >>= 1) v += __shfl_xor_sync(FULL, v, off);
        // theta0 twiddle
        float s0, c0;
        sincosf(act ? __ldg(theta + m) : 0.f, &s0, &c0);
        // rotation step e^{-2*pi*i*m/H}
        float ss, cs;
        sincosf(-2.0f * PIf * (float)m / (float)Hc, &ss, &cs);
        float curx = 1.f, cury = 0.f, Vx = 0.f, Vy = 0.f;
        #pragma unroll 4
        for (int k = 0; k < Hc; k++) {
            const float vrk = __shfl_sync(FULL, vr, k);
            const float vik = __shfl_sync(FULL, vi, k);
            Vx += vrk * curx - vik * cury;
            Vy += vrk * cury + vik * curx;
            const float nx = curx * cs - cury * ss;
            cury = curx * ss + cury * cs;
            curx = nx;
        }
        const float v0x =  __shfl_sync(FULL, vr, 0);   // conj(v1_0)
        const float v0y = -__shfl_sync(FULL, vi, 0);
        const float sc1 = 2.0f / v;
        const float gx = 1.0f - sc1 * (Vx * v0x - Vy * v0y);
        const float gy =        -sc1 * (Vx * v0y + Vy * v0x);
        const float inv_sqrt_h = 1.0f / sqrtf((float)Hc);
        if (act) {
            su[m]      = (c0 * gy + s0 * gx) * inv_sqrt_h;   // Im(e^{i th} g)
            su[m + Hc] = (c0 * gx - s0 * gy) * inv_sqrt_h;   // Re(e^{i th} g)
        }
    } else if (warp == 1) {
        // ---- B1 + vss2 + B2 + B3, entirely warp-internal ----
        const int k = lane;
        float s1, c1;
        sincosf(act ? __ldg(theta + Hc + k) : 0.f, &s1, &c1);
        const float z0x = c1 - s1, z0y = c1 + s1;            // own z0_k
        const float vr2 = act ? __ldg(refl + H2c + k)      : 0.f;
        const float vi2 = act ? __ldg(refl + H2c + Hc + k) : 0.f;
        float vss2 = vr2 * vr2 + vi2 * vi2;
        #pragma unroll
        for (int off = 16; off; off >>= 1) vss2 += __shfl_xor_sync(FULL, vss2, off);
        float s2v, c2v;
        sincosf(act ? __ldg(theta + 2 * Hc + k) : 0.f, &s2v, &c2v);
        bwr = act ? __ldg(Bw + k)      : 0.f;
        bwi = act ? __ldg(Bw + Hc + k) : 0.f;
        // B1: so_k = scale * sum_m z0_m e^{+2*pi*i*m*k/H} (rotation recurrence)
        float ssp, csp;
        sincosf(2.0f * PIf * (float)k / (float)Hc, &ssp, &csp);
        float curx = 1.f, cury = 0.f, ar = 0.f, ai = 0.f;
        #pragma unroll 4
        for (int m = 0; m < Hc; m++) {
            const float zxm = __shfl_sync(FULL, z0x, m);
            const float zym = __shfl_sync(FULL, z0y, m);
            ar += zxm * curx - zym * cury;
            ai += zxm * cury + zym * curx;
            const float nx = curx * csp - cury * ssp;
            cury = curx * ssp + cury * csp;
            curx = nx;
        }
        const float scale = 1.0f / ((float)Hc * sqrtf((float)Hc));
        const float orr = ar * scale, oii = ai * scale;
        // B2: t2 = (2/vss2) * (v2^T o)  (butterfly)
        float tx = vr2 * orr - vi2 * oii;
        float ty = vr2 * oii + vi2 * orr;
        #pragma unroll
        for (int off = 16; off; off >>= 1) {
            tx += __shfl_xor_sync(FULL, tx, off);
            ty += __shfl_xor_sync(FULL, ty, off);
        }
        const float sc2 = 2.0f / vss2;
        const float t2x = tx * sc2, t2y = ty * sc2;
        // B3: z = D3 * (o - t2*conj(v2))  (kept in regs across sync_a)
        if (act) {
            const float ox = orr - (t2x * vr2 + t2y * vi2);
            const float oy = oii - (t2y * vr2 - t2x * vi2);
            zr = ox * c2v - oy * s2v;
            zi = ox * s2v + oy * c2v;
        }
    }
    __syncthreads();                                      // sync_a: publishes su

    if (warp == 1) {
        // ---- C: alpha = u.z, beta = z.Bw; coefficient ladder ----
        const int k = lane;
        float ap = act ? su[k] * zr + su[Hc + k] * zi : 0.f;
        float bp = act ? zr * bwr + zi * bwi          : 0.f;
        #pragma unroll
        for (int off = 16; off; off >>= 1) {
            ap += __shfl_xor_sync(FULL, ap, off);
            bp += __shfl_xor_sync(FULL, bp, off);
        }
        if (lane < KT) {
            float c;
            if (lane == KT - 1) c = 1.0f;                 // slot for q
            else {
                c = bp;
                for (int e = 0; e < KT - 2 - lane; e++) c *= ap;
            }
            scoef[lane] = c;
        }
    }
    if (warp >= 4) {
        // ---- p = Cw^T u, q = Cw^T b ----
        const int d = tid - 128;
        float p = 0.f, q = 0.f;
        #pragma unroll 8
        for (int j = 0; j < H2c; j++) {
            const float cw = __ldg(Cw + j * Dc + d);
            p += su[j] * cw;
            q += __ldg(Bw + j) * cw;
        }
        sp[d] = p; sq[d] = q;
    }
    __syncthreads();                                      // sync_b: scoef, sp, sq

    // ---- Dot: k = (st + 64r) >> 5 = 2r + wis (warp-uniform) ----
    const float4 pv = reinterpret_cast<const float4*>(sp)[lane];
    const float4 qv = reinterpret_cast<const float4*>(sq)[lane];
    float acc = 0.f;
    #pragma unroll
    for (int r = 0; r < 8; r++) {
        const int k = 2 * r + wis;
        const float4 wv = (k == KT - 1) ? qv : pv;
        const float d = xv[r].x * wv.x + xv[r].y * wv.y
                      + xv[r].z * wv.z + xv[r].w * wv.w;
        acc += scoef[k] * d;
    }

    #pragma unroll
    for (int off = 16; off; off >>= 1) acc += __shfl_down_sync(FULL, acc, off);
    if (lane == 0) wsum[warp] = acc;
    __syncthreads();
    if (tid < ROWS_PER_BLK)
        out[blockIdx.x * ROWS_PER_BLK + tid] = wsum[2 * tid] + wsum[2 * tid + 1];
}

extern "C" void kernel_launch(void* const* d_in, const int* in_sizes, int n_in,
                              void* d_out, int out_size)
{
    const float* inputs = (const float*)d_in[0];   // (1024, 512, 128)
    const float* C_w    = (const float*)d_in[1];   // (40, 128)
    const float* B_w    = (const float*)d_in[2];   // (1, 40)
    const float* refl   = (const float*)d_in[3];   // (2, 40)
    const float* theta  = (const float*)d_in[4];   // (3, 20)
    const float* mu0    = (const float*)d_in[5];   // (20,)
    float* out = (float*)d_out;                    // (1024,)

    urnn_fused<<<Nc / ROWS_PER_BLK, 256>>>(inputs, C_w, B_w, refl, theta, mu0, out);
}